// round 6
// baseline (speedup 1.0000x reference)
#include <cuda_runtime.h>
#include <cstdint>

// Problem constants (B=2, C=1, D=128, H=256, W=256)
#define NVOL   2
#define DD     128
#define HH     256
#define WW     256
#define NB     (NVOL*DD*HH*WW)      // 16,777,216 voxels
#define WPR    (WW/32)              // 8 packed words per row
#define NWORDS (NVOL*DD*HH*WPR)     // 524,288 words (2 MB)
#define PW     10.0

#define P1_BLOCKS  512
#define P1_THREADS 512
#define P1_TOTAL   (P1_BLOCKS*P1_THREADS)   // 262,144 -> 16 quads/thread

// Fused dilation kernel geometry: one block = (volume, 4-row y-group), full z.
#define FD_THREADS 256
#define FD_YG      4
#define FD_BLOCKS  (NVOL * (HH / FD_YG))    // 128 blocks
#define RAW_STRIDE 84                        // words per z in raw tile (pad, 10*8=80 used)
#define RAW_WORDS  (DD * RAW_STRIDE)         // 10752
#define XY_WORDS   (DD * FD_YG * WPR)        // 4096
#define FD_SMEM    ((RAW_WORDS + XY_WORDS) * 4)   // 59392 bytes

// Scratch (allocation-free __device__ globals; zero-initialized at load)
__device__ unsigned int g_mask[NWORDS];
__device__ double g_base;      // sum |t-i| over all voxels
__device__ double g_corr;      // sum |t-i| over NOT-dilated voxels
__device__ unsigned int g_bcount;

// ---------------------------------------------------------------------------
// Pass 1: single streaming read of input+target (128 MB).
// Emits base = sum|t-i| and packed support mask (0 < t < 1).
// ---------------------------------------------------------------------------
__global__ void __launch_bounds__(P1_THREADS) pass1_kernel(
        const float4* __restrict__ inp,
        const float4* __restrict__ tgt) {
    int tid = blockIdx.x * blockDim.x + threadIdx.x;
    float base = 0.0f;

    #pragma unroll
    for (int g = 0; g < 4; ++g) {
        float4 a[4], b[4];
        int i0 = tid + g * 4 * P1_TOTAL;
        #pragma unroll
        for (int k = 0; k < 4; ++k) {
            int i = i0 + k * P1_TOTAL;
            a[k] = __ldcs(inp + i);
            b[k] = __ldcs(tgt + i);
        }
        #pragma unroll
        for (int k = 0; k < 4; ++k) {
            int i = i0 + k * P1_TOTAL;
            float dx = fabsf(b[k].x - a[k].x);
            float dy = fabsf(b[k].y - a[k].y);
            float dz = fabsf(b[k].z - a[k].z);
            float dw = fabsf(b[k].w - a[k].w);
            base += (dx + dy) + (dz + dw);

            unsigned nib =
                (unsigned)(b[k].x > 0.0f && b[k].x < 1.0f)
              | ((unsigned)(b[k].y > 0.0f && b[k].y < 1.0f) << 1)
              | ((unsigned)(b[k].z > 0.0f && b[k].z < 1.0f) << 2)
              | ((unsigned)(b[k].w > 0.0f && b[k].w < 1.0f) << 3);
            // 8 consecutive threads' nibbles -> one 32-bit word
            unsigned p  = nib | (__shfl_down_sync(0xFFFFFFFFu, nib, 1) << 4);
            unsigned p2 = p   | (__shfl_down_sync(0xFFFFFFFFu, p,   2) << 8);
            unsigned w  = p2  | (__shfl_down_sync(0xFFFFFFFFu, p2,  4) << 16);
            if ((threadIdx.x & 7) == 0) g_mask[i >> 3] = w;
        }
    }

    #pragma unroll
    for (int off = 16; off > 0; off >>= 1)
        base += __shfl_down_sync(0xFFFFFFFFu, base, off);
    __shared__ float ws[P1_THREADS / 32];
    int lane = threadIdx.x & 31, wid = threadIdx.x >> 5;
    if (lane == 0) ws[wid] = base;
    __syncthreads();
    if (wid == 0) {
        float s = (lane < P1_THREADS / 32) ? ws[lane] : 0.0f;
        #pragma unroll
        for (int off = 8; off > 0; off >>= 1)
            s += __shfl_down_sync(0xFFFFFFFFu, s, off);
        if (lane == 0) atomicAdd(&g_base, (double)s);
    }
}

// horizontal (x) dilation by +-3 bits across word boundaries
__device__ __forceinline__ unsigned hdil3(unsigned prev, unsigned cur, unsigned next) {
    unsigned r = cur;
    r |= (cur << 1) | (prev >> 31);
    r |= (cur << 2) | (prev >> 30);
    r |= (cur << 3) | (prev >> 29);
    r |= (cur >> 1) | (next << 31);
    r |= (cur >> 2) | (next << 30);
    r |= (cur >> 3) | (next << 29);
    return r;
}

// ---------------------------------------------------------------------------
// Fused dilation (xy + z) + complement correction + finalize.
// Block = (volume v, y-group of 4 rows), full z range in smem.
//   Phase A: load raw mask tile (z=128, y0-3..y0+6, 8 words) -> s_raw
//   Phase B: xy-dilation per (z,wx) column -> s_xy
//   Phase C: z-dilation (OR 7 z-neighbors, all in smem), complement,
//            gather |t-i| for unweighted voxels, reduce, finalize.
//   loss = 11*base - 10*corr ; out = loss/NB written by the last block.
// ---------------------------------------------------------------------------
__global__ void __launch_bounds__(FD_THREADS) dilate_fused_kernel(
        const float* __restrict__ inp,
        const float* __restrict__ tgt,
        float* __restrict__ out) {
    extern __shared__ unsigned smem[];
    unsigned* s_raw = smem;                 // [128][84] (80 used per z)
    unsigned* s_xy  = smem + RAW_WORDS;     // [128][4][8]

    int tid = threadIdx.x;
    int v   = blockIdx.x >> 6;              // volume
    int yg  = blockIdx.x & 63;              // y-group
    int y0  = yg << 2;

    // ---- Phase A: cooperative raw tile load (y halo zero-filled) ----
    const int base_row = y0 - 3;
    #pragma unroll
    for (int it = 0; it < (DD * 80) / FD_THREADS; ++it) {
        int i   = tid + it * FD_THREADS;    // 0 .. 10239
        int z   = i / 80;
        int rem = i - z * 80;               // yrel*8 + wx
        unsigned val = 0u;
        if ((unsigned)(base_row + (rem >> 3)) < HH) {
            // gword = ((v*128+z)*256 + base_row)*8 + rem
            int gword = (((v << 7) + z) << 11) + (base_row << 3) + rem;
            val = g_mask[gword];
        }
        s_raw[z * RAW_STRIDE + rem] = val;
    }
    __syncthreads();

    // ---- Phase B: xy dilation per (z, wx) column ----
    #pragma unroll
    for (int j = 0; j < 4; ++j) {
        int col = tid + j * FD_THREADS;     // 0 .. 1023
        int z   = col >> 3;
        int wx  = col & 7;
        const unsigned* rowp = &s_raw[z * RAW_STRIDE];
        unsigned hr[10];
        #pragma unroll
        for (int r = 0; r < 10; ++r) {
            unsigned cur  = rowp[r * 8 + wx];
            unsigned prev = (wx > 0) ? rowp[r * 8 + wx - 1] : 0u;
            unsigned next = (wx < 7) ? rowp[r * 8 + wx + 1] : 0u;
            hr[r] = hdil3(prev, cur, next);
        }
        #pragma unroll
        for (int k = 0; k < 4; ++k) {
            unsigned acc = hr[k];
            #pragma unroll
            for (int r = 1; r < 7; ++r) acc |= hr[k + r];
            s_xy[(z << 5) + (k << 3) + wx] = acc;
        }
    }
    __syncthreads();

    // ---- Phase C: z dilation + complement correction ----
    float corr = 0.0f;
    #pragma unroll
    for (int j = 0; j < XY_WORDS / FD_THREADS; ++j) {
        int w    = tid + j * FD_THREADS;    // 0 .. 4095
        int z    = w >> 5;
        int rest = w & 31;                  // ylocal*8 + wx
        unsigned acc = s_xy[w];
        #pragma unroll
        for (int dz = -3; dz <= 3; ++dz) {
            if (dz == 0) continue;
            int zz = z + dz;
            if ((unsigned)zz < DD) acc |= s_xy[(zz << 5) + rest];
        }
        unsigned miss = ~acc;               // unweighted voxels
        if (miss) {
            // global word index for (v, z, y0 + ylocal, wx)
            int gword = (((v << 7) + z) << 11) + (y0 << 3) + rest;
            int vox0 = gword << 5;
            do {
                int bit = __ffs(miss) - 1;
                miss &= miss - 1u;
                int i = vox0 + bit;
                corr += fabsf(tgt[i] - inp[i]);
            } while (miss);
        }
    }

    // ---- reduce + finalize ----
    #pragma unroll
    for (int off = 16; off > 0; off >>= 1)
        corr += __shfl_down_sync(0xFFFFFFFFu, corr, off);
    __shared__ float ws[FD_THREADS / 32];
    int lane = tid & 31, wid = tid >> 5;
    if (lane == 0) ws[wid] = corr;
    __syncthreads();
    if (wid == 0) {
        float s = (lane < FD_THREADS / 32) ? ws[lane] : 0.0f;
        #pragma unroll
        for (int off = 4; off > 0; off >>= 1)
            s += __shfl_down_sync(0xFFFFFFFFu, s, off);
        if (lane == 0) {
            atomicAdd(&g_corr, (double)s);
            __threadfence();
            unsigned prev = atomicAdd(&g_bcount, 1u);
            if (prev == gridDim.x - 1) {
                double total = (1.0 + PW) * g_base - PW * g_corr;
                out[0] = (float)(total / (double)NB);
                g_base = 0.0;        // reset for next graph replay
                g_corr = 0.0;
                g_bcount = 0u;
            }
        }
    }
}

extern "C" void kernel_launch(void* const* d_in, const int* in_sizes, int n_in,
                              void* d_out, int out_size) {
    const float* inp = (const float*)d_in[0];
    const float* tgt = (const float*)d_in[1];
    float* out = (float*)d_out;

    cudaFuncSetAttribute(dilate_fused_kernel,
                         cudaFuncAttributeMaxDynamicSharedMemorySize, FD_SMEM);

    pass1_kernel<<<P1_BLOCKS, P1_THREADS>>>((const float4*)inp, (const float4*)tgt);
    dilate_fused_kernel<<<FD_BLOCKS, FD_THREADS, FD_SMEM>>>(inp, tgt, out);
}

// round 7
// speedup vs baseline: 1.0693x; 1.0693x over previous
#include <cuda_runtime.h>
#include <cstdint>

// Problem constants (B=2, C=1, D=128, H=256, W=256)
#define NVOL   2
#define DD     128
#define HH     256
#define WW     256
#define NB     (NVOL*DD*HH*WW)      // 16,777,216 voxels
#define WPR    (WW/32)              // 8 packed words per row
#define NWORDS (NVOL*DD*HH*WPR)     // 524,288 words (2 MB)
#define PW     10.0

// Fine-grained blocks for wave balance: 2048 blocks x 256 thr = 524,288 threads,
// NQ = 4,194,304 quads -> exactly 8 quads/thread (2 groups of 4).
#define P1_BLOCKS  2048
#define P1_THREADS 256
#define P1_TOTAL   (P1_BLOCKS*P1_THREADS)

#define DZ_THREADS 256
#define DZ_BLOCKS  ((NWORDS / 4) / DZ_THREADS)   // 512 blocks

// Scratch (allocation-free __device__ globals; zero-initialized at load)
__device__ unsigned int g_mask[NWORDS];
__device__ unsigned int g_tmp[NWORDS];
__device__ double g_base;      // sum |t-i| over all voxels
__device__ double g_corr;      // sum |t-i| over NOT-dilated voxels
__device__ unsigned int g_bcount;

// ---------------------------------------------------------------------------
// Pass 1: single streaming read of input+target (128 MB).
// Emits base = sum|t-i| and packed support mask (0 < t < 1).
// ---------------------------------------------------------------------------
__global__ void __launch_bounds__(P1_THREADS) pass1_kernel(
        const float4* __restrict__ inp,
        const float4* __restrict__ tgt) {
    int tid = blockIdx.x * blockDim.x + threadIdx.x;
    float base = 0.0f;

    #pragma unroll
    for (int g = 0; g < 2; ++g) {
        float4 a[4], b[4];
        int i0 = tid + g * 4 * P1_TOTAL;
        #pragma unroll
        for (int k = 0; k < 4; ++k) {
            int i = i0 + k * P1_TOTAL;
            a[k] = __ldcs(inp + i);
            b[k] = __ldcs(tgt + i);
        }
        #pragma unroll
        for (int k = 0; k < 4; ++k) {
            int i = i0 + k * P1_TOTAL;
            float dx = fabsf(b[k].x - a[k].x);
            float dy = fabsf(b[k].y - a[k].y);
            float dz = fabsf(b[k].z - a[k].z);
            float dw = fabsf(b[k].w - a[k].w);
            base += (dx + dy) + (dz + dw);

            unsigned nib =
                (unsigned)(b[k].x > 0.0f && b[k].x < 1.0f)
              | ((unsigned)(b[k].y > 0.0f && b[k].y < 1.0f) << 1)
              | ((unsigned)(b[k].z > 0.0f && b[k].z < 1.0f) << 2)
              | ((unsigned)(b[k].w > 0.0f && b[k].w < 1.0f) << 3);
            // 8 consecutive threads' nibbles -> one 32-bit word
            unsigned p  = nib | (__shfl_down_sync(0xFFFFFFFFu, nib, 1) << 4);
            unsigned p2 = p   | (__shfl_down_sync(0xFFFFFFFFu, p,   2) << 8);
            unsigned w  = p2  | (__shfl_down_sync(0xFFFFFFFFu, p2,  4) << 16);
            if ((threadIdx.x & 7) == 0) g_mask[i >> 3] = w;
        }
    }

    #pragma unroll
    for (int off = 16; off > 0; off >>= 1)
        base += __shfl_down_sync(0xFFFFFFFFu, base, off);
    __shared__ float ws[P1_THREADS / 32];
    int lane = threadIdx.x & 31, wid = threadIdx.x >> 5;
    if (lane == 0) ws[wid] = base;
    __syncthreads();
    if (wid == 0) {
        float s = (lane < P1_THREADS / 32) ? ws[lane] : 0.0f;
        #pragma unroll
        for (int off = 4; off > 0; off >>= 1)
            s += __shfl_down_sync(0xFFFFFFFFu, s, off);
        if (lane == 0) atomicAdd(&g_base, (double)s);
    }
}

// horizontal (x) dilation by +-3 bits across word boundaries
__device__ __forceinline__ unsigned hdil3(unsigned prev, unsigned cur, unsigned next) {
    unsigned r = cur;
    r |= (cur << 1) | (prev >> 31);
    r |= (cur << 2) | (prev >> 30);
    r |= (cur << 3) | (prev >> 29);
    r |= (cur >> 1) | (next << 31);
    r |= (cur >> 2) | (next << 30);
    r |= (cur >> 3) | (next << 29);
    return r;
}

// ---------------------------------------------------------------------------
// x+y dilation, 4 y-outputs per thread. g_mask -> g_tmp.
// ---------------------------------------------------------------------------
__global__ void dilate_xy_kernel() {
    int t = blockIdx.x * blockDim.x + threadIdx.x;    // 131072 threads
    int wx = t & 7;
    int yg = (t >> 3) & 63;
    int vz = t >> 9;                                  // v*DD+z, 0..255
    int rowbase = vz << 11;
    int y0 = yg << 2;

    unsigned hr[10];
    #pragma unroll
    for (int r = 0; r < 10; ++r) {
        int yy = y0 - 3 + r;
        if (yy < 0 || yy >= HH) { hr[r] = 0u; continue; }
        int base = rowbase + (yy << 3);
        unsigned cur  = g_mask[base + wx];
        unsigned prev = (wx > 0) ? g_mask[base + wx - 1] : 0u;
        unsigned next = (wx < 7) ? g_mask[base + wx + 1] : 0u;
        hr[r] = hdil3(prev, cur, next);
    }
    #pragma unroll
    for (int k = 0; k < 4; ++k) {
        unsigned acc = hr[k];
        #pragma unroll
        for (int r = 1; r < 7; ++r) acc |= hr[k + r];
        g_tmp[rowbase + ((y0 + k) << 3) + wx] = acc;
    }
}

// ---------------------------------------------------------------------------
// Fused z-dilation + complement correction + finalize.
// For each output word: OR 7 z-neighbors of g_tmp; zero bits of the result
// are the unweighted voxels -> gather their |t-i| directly (rare).
//   loss = 11*base - 10*corr ; out = loss/NB written by the last block.
// ---------------------------------------------------------------------------
__global__ void __launch_bounds__(DZ_THREADS) dilate_z_corr_kernel(
        const float* __restrict__ inp,
        const float* __restrict__ tgt,
        float* __restrict__ out) {
    int t = blockIdx.x * blockDim.x + threadIdx.x;    // 131072 threads
    int wxy = t & 2047;                               // word within z-slice
    int zg  = (t >> 11) & 31;
    int v   = t >> 16;
    int z0  = zg << 2;

    unsigned c[10];
    #pragma unroll
    for (int r = 0; r < 10; ++r) {
        int zz = z0 - 3 + r;
        c[r] = (zz >= 0 && zz < DD) ? g_tmp[(((v << 7) + zz) << 11) + wxy] : 0u;
    }

    float corr = 0.0f;
    #pragma unroll
    for (int k = 0; k < 4; ++k) {
        unsigned acc = c[k];
        #pragma unroll
        for (int r = 1; r < 7; ++r) acc |= c[k + r];
        unsigned miss = ~acc;                         // unweighted voxels
        if (miss) {
            int wordidx = (((v << 7) + (z0 + k)) << 11) + wxy;
            int vox0 = wordidx << 5;
            do {
                int bit = __ffs(miss) - 1;
                miss &= miss - 1u;
                int i = vox0 + bit;
                corr += fabsf(tgt[i] - inp[i]);
            } while (miss);
        }
    }

    #pragma unroll
    for (int off = 16; off > 0; off >>= 1)
        corr += __shfl_down_sync(0xFFFFFFFFu, corr, off);
    __shared__ float ws[DZ_THREADS / 32];
    int lane = threadIdx.x & 31, wid = threadIdx.x >> 5;
    if (lane == 0) ws[wid] = corr;
    __syncthreads();
    if (wid == 0) {
        float s = (lane < DZ_THREADS / 32) ? ws[lane] : 0.0f;
        #pragma unroll
        for (int off = 4; off > 0; off >>= 1)
            s += __shfl_down_sync(0xFFFFFFFFu, s, off);
        if (lane == 0) {
            atomicAdd(&g_corr, (double)s);
            __threadfence();
            unsigned prev = atomicAdd(&g_bcount, 1u);
            if (prev == gridDim.x - 1) {
                double total = (1.0 + PW) * g_base - PW * g_corr;
                out[0] = (float)(total / (double)NB);
                g_base = 0.0;        // reset for next graph replay
                g_corr = 0.0;
                g_bcount = 0u;
            }
        }
    }
}

extern "C" void kernel_launch(void* const* d_in, const int* in_sizes, int n_in,
                              void* d_out, int out_size) {
    const float* inp = (const float*)d_in[0];
    const float* tgt = (const float*)d_in[1];
    float* out = (float*)d_out;

    pass1_kernel<<<P1_BLOCKS, P1_THREADS>>>((const float4*)inp, (const float4*)tgt);
    dilate_xy_kernel<<<(NWORDS / 4) / 256, 256>>>();
    dilate_z_corr_kernel<<<DZ_BLOCKS, DZ_THREADS>>>(inp, tgt, out);
}